// round 4
// baseline (speedup 1.0000x reference)
#include <cuda_runtime.h>

// Model_55645596287458: rotate 4M points into camera frame, mask by
// depth (1,10) + FOV, emit masked verts [N,3] and loss = 1/(sum(obs)+eps).
//
// R4: smem-staged coalesced I/O. Block = 256 threads = 1024 points.
//  phase 1: 3x coalesced LDG.128 -> padded smem tile
//  phase 2: per-thread compute from smem (strided, pad kills conflicts),
//           results written back in-place (thread-private slots)
//  phase 3: 3x coalesced STG.128 from smem
// Division-free mask (compare ph against v2-scaled bounds), rsqrt distance.

__device__ float        g_sum   = 0.0f;
__device__ unsigned int g_count = 0u;

#define PAD4(q) ((q) + ((q) >> 3))   // one float4 hole per 8 -> debanks stride-12 reads

__global__ __launch_bounds__(256) void pose_obs_kernel(
    const float* __restrict__ pts,
    const float* __restrict__ px,  const float* __restrict__ py,
    const float* __restrict__ pz,  const float* __restrict__ proll,
    const float* __restrict__ ppitch, const float* __restrict__ pyaw,
    float* __restrict__ out, int n_pts, int loss_idx)
{
    __shared__ float4 tile[PAD4(768)];   // 864 float4 = 13.8 KB
    __shared__ float  sRT[12];
    __shared__ float  swarp[8];

    const int t = threadIdx.x;

    if (t == 0) {
        float roll = *proll, pitch = *ppitch, yaw = *pyaw;
        float cr = cosf(roll),  sr = sinf(roll);
        float cp = cosf(pitch), sp = sinf(pitch);
        float cy = cosf(yaw),   sy = sinf(yaw);
        // R = Rx @ Ry @ Rz (row-major)
        sRT[0] = cp * cy;                sRT[1] = -cp * sy;               sRT[2] = sp;
        sRT[3] = cr * sy + sr * sp * cy; sRT[4] = cr * cy - sr * sp * sy; sRT[5] = -sr * cp;
        sRT[6] = sr * sy - cr * sp * cy; sRT[7] = sr * cy + cr * sp * sy; sRT[8] = cr * cp;
        sRT[9] = *px; sRT[10] = *py; sRT[11] = *pz;
    }

    const int n_groups = n_pts >> 2;              // threads doing 4 pts each
    const int nF4      = 3 * n_groups;            // total float4s in stream
    const int baseF4   = blockIdx.x * 768;
    const float4* __restrict__ P4 = (const float4*)pts;
    float4* __restrict__ O4 = (float4*)out;

    // ---- phase 1: coalesced load into padded smem tile ----
    #pragma unroll
    for (int k = 0; k < 3; k++) {
        const int q = k * 256 + t;
        if (baseF4 + q < nF4)
            tile[PAD4(q)] = P4[baseF4 + q];
    }
    __syncthreads();

    const float R00 = sRT[0], R01 = sRT[1], R02 = sRT[2];
    const float R10 = sRT[3], R11 = sRT[4], R12 = sRT[5];
    const float R20 = sRT[6], R21 = sRT[7], R22 = sRT[8];
    const float Tx  = sRT[9], Ty  = sRT[10], Tz = sRT[11];

    const int g = blockIdx.x * 256 + t;
    float obs_sum = 0.0f;

    // ---- phase 2: compute 4 points from thread-private smem slots ----
    if (g < n_groups) {
        const float4 a = tile[PAD4(3 * t + 0)];
        const float4 b = tile[PAD4(3 * t + 1)];
        const float4 c = tile[PAD4(3 * t + 2)];
        const float p[12] = {a.x, a.y, a.z, a.w, b.x, b.y, b.z, b.w,
                             c.x, c.y, c.z, c.w};
        float o[12];

        #pragma unroll
        for (int i = 0; i < 4; i++) {
            const float d0 = p[3 * i + 0] - Tx;
            const float d1 = p[3 * i + 1] - Ty;
            const float d2 = p[3 * i + 2] - Tz;
            // v = d @ R  (v_j = sum_i d_i * R[i][j])
            const float v0 = fmaf(d2, R20, fmaf(d1, R10, d0 * R00));
            const float v1 = fmaf(d2, R21, fmaf(d1, R11, d0 * R01));
            const float v2 = fmaf(d2, R22, fmaf(d1, R12, d0 * R02));

            // ph = v @ K^T ; ph2 == v2 exactly (K row 2 = [0,0,1])
            const float ph0 = fmaf(600.0f, v0, 640.0f * v2);
            const float ph1 = fmaf(600.0f, v1, 360.0f * v2);

            // division-free mask: requires v2 > 1 (> 0), so
            //   u > 1     <=> ph0 > v2        u < 1279 <=> ph0 < 1279*v2
            //   w > 1     <=> ph1 > v2        w < 719  <=> ph1 < 719*v2
            const bool m = (v2 > 1.0f) & (v2 < 10.0f) &
                           (ph0 > v2) & (ph0 < 1279.0f * v2) &
                           (ph1 > v2) & (ph1 < 719.0f * v2);

            const float n2 = fmaf(v0, v0, fmaf(v1, v1, v2 * v2));
            const float dist = n2 * rsqrtf(n2);
            const float tt = fmaf(dist, 0.5f, -2.0f);     // (d-4)/2
            const float e = __expf(-0.5f * tt * tt);
            obs_sum += m ? e : 0.0f;

            o[3 * i + 0] = m ? v0 : 0.0f;
            o[3 * i + 1] = m ? v1 : 0.0f;
            o[3 * i + 2] = m ? v2 : 0.0f;
        }

        // in-place writeback (thread-private slots -> no hazard)
        tile[PAD4(3 * t + 0)] = make_float4(o[0], o[1], o[2],  o[3]);
        tile[PAD4(3 * t + 1)] = make_float4(o[4], o[5], o[6],  o[7]);
        tile[PAD4(3 * t + 2)] = make_float4(o[8], o[9], o[10], o[11]);

        // Tail (n_pts not divisible by 4): scalar path on thread 0.
        if (g == 0) {
            for (int idx = n_groups * 4; idx < n_pts; idx++) {
                const float d0 = pts[3 * idx + 0] - Tx;
                const float d1 = pts[3 * idx + 1] - Ty;
                const float d2 = pts[3 * idx + 2] - Tz;
                const float v0 = fmaf(d2, R20, fmaf(d1, R10, d0 * R00));
                const float v1 = fmaf(d2, R21, fmaf(d1, R11, d0 * R01));
                const float v2 = fmaf(d2, R22, fmaf(d1, R12, d0 * R02));
                const float ph0 = fmaf(600.0f, v0, 640.0f * v2);
                const float ph1 = fmaf(600.0f, v1, 360.0f * v2);
                const bool m = (v2 > 1.0f) & (v2 < 10.0f) &
                               (ph0 > v2) & (ph0 < 1279.0f * v2) &
                               (ph1 > v2) & (ph1 < 719.0f * v2);
                const float n2 = fmaf(v0, v0, fmaf(v1, v1, v2 * v2));
                const float dist = n2 * rsqrtf(n2);
                const float tt = fmaf(dist, 0.5f, -2.0f);
                obs_sum += m ? __expf(-0.5f * tt * tt) : 0.0f;
                out[3 * idx + 0] = m ? v0 : 0.0f;
                out[3 * idx + 1] = m ? v1 : 0.0f;
                out[3 * idx + 2] = m ? v2 : 0.0f;
            }
        }
    }
    __syncthreads();

    // ---- phase 3: coalesced store from smem tile ----
    #pragma unroll
    for (int k = 0; k < 3; k++) {
        const int q = k * 256 + t;
        if (baseF4 + q < nF4)
            O4[baseF4 + q] = tile[PAD4(q)];
    }

    // ---- reduction: warp -> block -> global atomic ----
    #pragma unroll
    for (int off = 16; off > 0; off >>= 1)
        obs_sum += __shfl_xor_sync(0xffffffffu, obs_sum, off);

    const int lane = t & 31;
    const int wid  = t >> 5;
    if (lane == 0) swarp[wid] = obs_sum;
    __syncthreads();

    if (wid == 0) {
        float s = (lane < 8) ? swarp[lane] : 0.0f;
        #pragma unroll
        for (int off = 4; off > 0; off >>= 1)
            s += __shfl_xor_sync(0xffu, s, off);
        if (lane == 0) {
            atomicAdd(&g_sum, s);
            __threadfence();
            const unsigned int prev = atomicAdd(&g_count, 1u);
            if (prev == gridDim.x - 1u) {
                const float total = atomicAdd(&g_sum, 0.0f);
                out[loss_idx] = 1.0f / (total + 1e-6f);
                g_sum = 0.0f;       // reset for next graph replay
                g_count = 0u;
            }
        }
    }
}

extern "C" void kernel_launch(void* const* d_in, const int* in_sizes, int n_in,
                              void* d_out, int out_size) {
    const float* pts    = (const float*)d_in[0];
    const float* x      = (const float*)d_in[1];
    const float* y      = (const float*)d_in[2];
    const float* z      = (const float*)d_in[3];
    const float* roll   = (const float*)d_in[4];
    const float* pitch  = (const float*)d_in[5];
    const float* yaw    = (const float*)d_in[6];
    float* out = (float*)d_out;

    const int n_pts = in_sizes[0] / 3;       // 4,000,000
    const int n_groups = n_pts >> 2;         // 1,000,000 threads (4 pts each)
    const int threads = 256;
    const int blocks = (n_groups + threads - 1) / threads;
    const int loss_idx = out_size - 1;       // verts first, loss last

    pose_obs_kernel<<<blocks, threads>>>(pts, x, y, z, roll, pitch, yaw,
                                         out, n_pts, loss_idx);
}

// round 5
// speedup vs baseline: 1.0365x; 1.0365x over previous
#include <cuda_runtime.h>
#include <cstdint>

// Model_55645596287458 — R5: persistent TMA bulk pipeline.
// 148 CTAs x 768 threads, one CTA/SM (166KB smem).
//  - 6-stage cp.async.bulk input ring (18KB tiles = 1536 pts)
//  - compute 2 pts/thread from smem (division-free mask, rsqrt dist)
//  - 3-stage cp.async.bulk output ring (bulk_group backpressure)
// Loss = 1/(sum(obs)+eps) via per-thread accum -> block -> atomic, last
// block finalizes and resets globals (graph-replay safe).

#define IN_STG     6
#define OUT_STG    3
#define TILE_PTS   1536
#define TILE_BYTES (TILE_PTS * 12)      // 18432
#define THREADS    768
#define NBLK       148
#define SMEM_DYN   ((IN_STG + OUT_STG) * TILE_BYTES + IN_STG * 8)

__device__ float        g_sum   = 0.0f;
__device__ unsigned int g_count = 0u;

__device__ __forceinline__ void mbar_init(uint32_t a, uint32_t cnt) {
    asm volatile("mbarrier.init.shared.b64 [%0], %1;" :: "r"(a), "r"(cnt) : "memory");
}
__device__ __forceinline__ void mbar_expect_tx(uint32_t a, uint32_t bytes) {
    asm volatile("mbarrier.arrive.expect_tx.shared.b64 _, [%0], %1;"
                 :: "r"(a), "r"(bytes) : "memory");
}
__device__ __forceinline__ void mbar_wait_parity(uint32_t a, uint32_t parity) {
    asm volatile(
        "{\n\t.reg .pred P;\n\t"
        "LW_%=:\n\t"
        "mbarrier.try_wait.parity.acquire.cta.shared::cta.b64 P, [%0], %1, 0x989680;\n\t"
        "@P bra.uni LD_%=;\n\t"
        "bra.uni LW_%=;\n\t"
        "LD_%=:\n\t}"
        :: "r"(a), "r"(parity) : "memory");
}
__device__ __forceinline__ void bulk_g2s(uint32_t dst, const void* src,
                                         uint32_t bytes, uint32_t mbar) {
    asm volatile("cp.async.bulk.shared::cta.global.mbarrier::complete_tx::bytes "
                 "[%0], [%1], %2, [%3];"
                 :: "r"(dst), "l"(src), "r"(bytes), "r"(mbar) : "memory");
}
__device__ __forceinline__ void bulk_s2g(void* dst, uint32_t src, uint32_t bytes) {
    asm volatile("cp.async.bulk.global.shared::cta.bulk_group [%0], [%1], %2;"
                 :: "l"(dst), "r"(src), "r"(bytes) : "memory");
}

extern __shared__ char smem_raw[];

__global__ __launch_bounds__(THREADS, 1) void pose_tma_kernel(
    const float* __restrict__ pts,
    const float* __restrict__ px,  const float* __restrict__ py,
    const float* __restrict__ pz,  const float* __restrict__ proll,
    const float* __restrict__ ppitch, const float* __restrict__ pyaw,
    float* __restrict__ out, int n_pts, int loss_idx)
{
    __shared__ float sRT[12];
    __shared__ float swarp[THREADS / 32];

    const int t = threadIdx.x;
    const int bid = blockIdx.x;

    char* in_base  = smem_raw;
    char* out_base = smem_raw + IN_STG * TILE_BYTES;
    const uint32_t mbar_base =
        (uint32_t)__cvta_generic_to_shared(smem_raw + (IN_STG + OUT_STG) * TILE_BYTES);

    if (t == 0) {
        float roll = *proll, pitch = *ppitch, yaw = *pyaw;
        float cr = cosf(roll),  sr = sinf(roll);
        float cp = cosf(pitch), sp = sinf(pitch);
        float cy = cosf(yaw),   sy = sinf(yaw);
        // R = Rx @ Ry @ Rz (row-major)
        sRT[0] = cp * cy;                sRT[1] = -cp * sy;               sRT[2] = sp;
        sRT[3] = cr * sy + sr * sp * cy; sRT[4] = cr * cy - sr * sp * sy; sRT[5] = -sr * cp;
        sRT[6] = sr * sy - cr * sp * cy; sRT[7] = sr * cy + cr * sp * sy; sRT[8] = cr * cp;
        sRT[9] = *px; sRT[10] = *py; sRT[11] = *pz;
        #pragma unroll
        for (int s = 0; s < IN_STG; s++) mbar_init(mbar_base + 8 * s, 1);
    }
    __syncthreads();

    const float R00 = sRT[0], R01 = sRT[1], R02 = sRT[2];
    const float R10 = sRT[3], R11 = sRT[4], R12 = sRT[5];
    const float R20 = sRT[6], R21 = sRT[7], R22 = sRT[8];
    const float Tx  = sRT[9], Ty  = sRT[10], Tz = sRT[11];

    const int n_main  = n_pts & ~3;                       // bulk-copyable portion
    const int n_tiles = (n_main + TILE_PTS - 1) / TILE_PTS;
    const int my_count = (bid < n_tiles) ? (n_tiles - bid + NBLK - 1) / NBLK : 0;

    // ---- prefetch first IN_STG tiles ----
    if (t == 0) {
        const int pre = my_count < IN_STG ? my_count : IN_STG;
        for (int j = 0; j < pre; j++) {
            const int tile = bid + j * NBLK;
            const int tp   = min(TILE_PTS, n_main - tile * TILE_PTS);
            const uint32_t bytes = (uint32_t)tp * 12u;
            mbar_expect_tx(mbar_base + 8 * j, bytes);
            bulk_g2s((uint32_t)__cvta_generic_to_shared(in_base + j * TILE_BYTES),
                     pts + (size_t)tile * TILE_PTS * 3, bytes, mbar_base + 8 * j);
        }
    }

    float obs_sum = 0.0f;

    for (int j = 0; j < my_count; j++) {
        const int tile  = bid + j * NBLK;
        const int tp    = min(TILE_PTS, n_main - tile * TILE_PTS);
        const int stage = j % IN_STG;
        const int oslot = j % OUT_STG;

        if (t == 0) {
            mbar_wait_parity(mbar_base + 8 * stage, (uint32_t)((j / IN_STG) & 1));
            asm volatile("cp.async.bulk.wait_group.read 2;" ::: "memory"); // OUT_STG-1
        }
        __syncthreads();   // in-tile ready, out slot free, for all threads

        const float2* __restrict__ in2 =
            (const float2*)(in_base + stage * TILE_BYTES);
        float2* __restrict__ out2 = (float2*)(out_base + oslot * TILE_BYTES);

        if (2 * t < tp) {
            const float2 sa = in2[3 * t + 0];
            const float2 sb = in2[3 * t + 1];
            const float2 sc = in2[3 * t + 2];
            const float p[6] = {sa.x, sa.y, sb.x, sb.y, sc.x, sc.y};
            float o[6];

            #pragma unroll
            for (int i = 0; i < 2; i++) {
                const float d0 = p[3 * i + 0] - Tx;
                const float d1 = p[3 * i + 1] - Ty;
                const float d2 = p[3 * i + 2] - Tz;
                const float v0 = fmaf(d2, R20, fmaf(d1, R10, d0 * R00));
                const float v1 = fmaf(d2, R21, fmaf(d1, R11, d0 * R01));
                const float v2 = fmaf(d2, R22, fmaf(d1, R12, d0 * R02));

                const float ph0 = fmaf(600.0f, v0, 640.0f * v2);
                const float ph1 = fmaf(600.0f, v1, 360.0f * v2);
                // division-free: v2>1 (>0) makes these equivalent to u/w bounds
                const bool m = (v2 > 1.0f) & (v2 < 10.0f) &
                               (ph0 > v2) & (ph0 < 1279.0f * v2) &
                               (ph1 > v2) & (ph1 < 719.0f * v2);
                const bool valid = m & ((2 * t + i) < tp);

                const float n2 = fmaf(v0, v0, fmaf(v1, v1, v2 * v2));
                const float dist = n2 * rsqrtf(n2);
                const float tt = fmaf(dist, 0.5f, -2.0f);       // (d-4)/2
                const float e = __expf(-0.5f * tt * tt);
                obs_sum += valid ? e : 0.0f;

                o[3 * i + 0] = valid ? v0 : 0.0f;
                o[3 * i + 1] = valid ? v1 : 0.0f;
                o[3 * i + 2] = valid ? v2 : 0.0f;
            }
            out2[3 * t + 0] = make_float2(o[0], o[1]);
            out2[3 * t + 1] = make_float2(o[2], o[3]);
            out2[3 * t + 2] = make_float2(o[4], o[5]);
        }

        // generic->async proxy ordering for the out tile
        asm volatile("fence.proxy.async.shared::cta;" ::: "memory");
        __syncthreads();   // in-tile fully consumed, out-tile fully written

        if (t == 0) {
            const int jn = j + IN_STG;
            if (jn < my_count) {
                const int tile_n = bid + jn * NBLK;
                const int tp_n   = min(TILE_PTS, n_main - tile_n * TILE_PTS);
                const uint32_t bytes_n = (uint32_t)tp_n * 12u;
                mbar_expect_tx(mbar_base + 8 * stage, bytes_n);
                bulk_g2s((uint32_t)__cvta_generic_to_shared(in_base + stage * TILE_BYTES),
                         pts + (size_t)tile_n * TILE_PTS * 3, bytes_n,
                         mbar_base + 8 * stage);
            }
            bulk_s2g(out + (size_t)tile * TILE_PTS * 3,
                     (uint32_t)__cvta_generic_to_shared(out_base + oslot * TILE_BYTES),
                     (uint32_t)tp * 12u);
            asm volatile("cp.async.bulk.commit_group;" ::: "memory");
        }
    }

    if (t == 0) {
        asm volatile("cp.async.bulk.wait_group.read 0;" ::: "memory");
    }

    // ---- tail points (n_pts % 4): scalar on block 0 / thread 0 ----
    if (bid == 0 && t == 0) {
        for (int idx = n_main; idx < n_pts; idx++) {
            const float d0 = pts[3 * idx + 0] - Tx;
            const float d1 = pts[3 * idx + 1] - Ty;
            const float d2 = pts[3 * idx + 2] - Tz;
            const float v0 = fmaf(d2, R20, fmaf(d1, R10, d0 * R00));
            const float v1 = fmaf(d2, R21, fmaf(d1, R11, d0 * R01));
            const float v2 = fmaf(d2, R22, fmaf(d1, R12, d0 * R02));
            const float ph0 = fmaf(600.0f, v0, 640.0f * v2);
            const float ph1 = fmaf(600.0f, v1, 360.0f * v2);
            const bool m = (v2 > 1.0f) & (v2 < 10.0f) &
                           (ph0 > v2) & (ph0 < 1279.0f * v2) &
                           (ph1 > v2) & (ph1 < 719.0f * v2);
            const float n2 = fmaf(v0, v0, fmaf(v1, v1, v2 * v2));
            const float dist = n2 * rsqrtf(n2);
            const float tt = fmaf(dist, 0.5f, -2.0f);
            obs_sum += m ? __expf(-0.5f * tt * tt) : 0.0f;
            out[3 * idx + 0] = m ? v0 : 0.0f;
            out[3 * idx + 1] = m ? v1 : 0.0f;
            out[3 * idx + 2] = m ? v2 : 0.0f;
        }
    }

    // ---- reduction: warp -> block -> global atomic ----
    #pragma unroll
    for (int off = 16; off > 0; off >>= 1)
        obs_sum += __shfl_xor_sync(0xffffffffu, obs_sum, off);

    const int lane = t & 31;
    const int wid  = t >> 5;
    if (lane == 0) swarp[wid] = obs_sum;
    __syncthreads();

    if (wid == 0) {
        float s = (lane < THREADS / 32) ? swarp[lane] : 0.0f;
        #pragma unroll
        for (int off = 16; off > 0; off >>= 1)
            s += __shfl_xor_sync(0xffffffffu, s, off);
        if (lane == 0) {
            atomicAdd(&g_sum, s);
            __threadfence();
            const unsigned int prev = atomicAdd(&g_count, 1u);
            if (prev == gridDim.x - 1u) {
                const float total = atomicAdd(&g_sum, 0.0f);
                out[loss_idx] = 1.0f / (total + 1e-6f);
                g_sum = 0.0f;       // reset for next graph replay
                g_count = 0u;
            }
        }
    }
}

extern "C" void kernel_launch(void* const* d_in, const int* in_sizes, int n_in,
                              void* d_out, int out_size) {
    const float* pts    = (const float*)d_in[0];
    const float* x      = (const float*)d_in[1];
    const float* y      = (const float*)d_in[2];
    const float* z      = (const float*)d_in[3];
    const float* roll   = (const float*)d_in[4];
    const float* pitch  = (const float*)d_in[5];
    const float* yaw    = (const float*)d_in[6];
    float* out = (float*)d_out;

    const int n_pts = in_sizes[0] / 3;       // 4,000,000
    const int loss_idx = out_size - 1;       // verts first, loss last

    cudaFuncSetAttribute(pose_tma_kernel,
                         cudaFuncAttributeMaxDynamicSharedMemorySize, SMEM_DYN);
    pose_tma_kernel<<<NBLK, THREADS, SMEM_DYN>>>(pts, x, y, z, roll, pitch, yaw,
                                                 out, n_pts, loss_idx);
}

// round 7
// speedup vs baseline: 1.3701x; 1.3219x over previous
#include <cuda_runtime.h>
#include <cstdint>

// Model_55645596287458 — R6b (resubmit; R6 bench died to container infra).
// Warp-private TMA pipelines, no CTA barriers in the hot loop.
// 148 CTAs x 512 threads; each of the 16 warps owns a 4-slot x 3KB
// (256-pt) smem ring:
//   g2s bulk load (3-deep prefetch) -> in-place compute (8 pts/lane)
//   -> bulk store (per-warp bulk_group chain, wait_group.read 1 recycles).

#define WARPS     16
#define THREADS   (WARPS * 32)
#define SLOTS     4
#define TILE_PTS  256
#define TILE_B    (TILE_PTS * 12)            // 3072
#define NBLK      148
#define PREF      3
#define SMEM_TILES (WARPS * SLOTS * TILE_B)  // 196608
#define SMEM_DYN   (SMEM_TILES + WARPS * SLOTS * 8)

__device__ float        g_sum   = 0.0f;
__device__ unsigned int g_count = 0u;

__device__ __forceinline__ void mbar_init(uint32_t a, uint32_t cnt) {
    asm volatile("mbarrier.init.shared.b64 [%0], %1;" :: "r"(a), "r"(cnt) : "memory");
}
__device__ __forceinline__ void mbar_expect_tx(uint32_t a, uint32_t bytes) {
    asm volatile("mbarrier.arrive.expect_tx.shared.b64 _, [%0], %1;"
                 :: "r"(a), "r"(bytes) : "memory");
}
__device__ __forceinline__ void mbar_wait_parity(uint32_t a, uint32_t parity) {
    asm volatile(
        "{\n\t.reg .pred P;\n\t"
        "LW_%=:\n\t"
        "mbarrier.try_wait.parity.acquire.cta.shared::cta.b64 P, [%0], %1, 0x989680;\n\t"
        "@P bra.uni LD_%=;\n\t"
        "bra.uni LW_%=;\n\t"
        "LD_%=:\n\t}"
        :: "r"(a), "r"(parity) : "memory");
}
__device__ __forceinline__ void bulk_g2s(uint32_t dst, const void* src,
                                         uint32_t bytes, uint32_t mbar) {
    asm volatile("cp.async.bulk.shared::cta.global.mbarrier::complete_tx::bytes "
                 "[%0], [%1], %2, [%3];"
                 :: "r"(dst), "l"(src), "r"(bytes), "r"(mbar) : "memory");
}
__device__ __forceinline__ void bulk_s2g(void* dst, uint32_t src, uint32_t bytes) {
    asm volatile("cp.async.bulk.global.shared::cta.bulk_group [%0], [%1], %2;"
                 :: "l"(dst), "r"(src), "r"(bytes) : "memory");
}

extern __shared__ char smem_raw[];

__global__ __launch_bounds__(THREADS, 1) void pose_warp_pipe_kernel(
    const float* __restrict__ pts,
    const float* __restrict__ px,  const float* __restrict__ py,
    const float* __restrict__ pz,  const float* __restrict__ proll,
    const float* __restrict__ ppitch, const float* __restrict__ pyaw,
    float* __restrict__ out, int n_pts, int loss_idx)
{
    __shared__ float sRT[12];
    __shared__ float swarp[WARPS];

    const int t    = threadIdx.x;
    const int lane = t & 31;
    const int wid  = t >> 5;
    const int bid  = blockIdx.x;

    const uint32_t smem_base = (uint32_t)__cvta_generic_to_shared(smem_raw);
    const uint32_t mbar_base = smem_base + SMEM_TILES;

    if (t == 0) {
        float roll = *proll, pitch = *ppitch, yaw = *pyaw;
        float cr = cosf(roll),  sr = sinf(roll);
        float cp = cosf(pitch), sp = sinf(pitch);
        float cy = cosf(yaw),   sy = sinf(yaw);
        // R = Rx @ Ry @ Rz (row-major)
        sRT[0] = cp * cy;                sRT[1] = -cp * sy;               sRT[2] = sp;
        sRT[3] = cr * sy + sr * sp * cy; sRT[4] = cr * cy - sr * sp * sy; sRT[5] = -sr * cp;
        sRT[6] = sr * sy - cr * sp * cy; sRT[7] = sr * cy + cr * sp * sy; sRT[8] = cr * cp;
        sRT[9] = *px; sRT[10] = *py; sRT[11] = *pz;
    }
    if (t < WARPS * SLOTS) mbar_init(mbar_base + 8u * t, 1);
    __syncthreads();   // only CTA-wide sync before the final reduction

    const float R00 = sRT[0], R01 = sRT[1], R02 = sRT[2];
    const float R10 = sRT[3], R11 = sRT[4], R12 = sRT[5];
    const float R20 = sRT[6], R21 = sRT[7], R22 = sRT[8];
    const float Tx  = sRT[9], Ty  = sRT[10], Tz = sRT[11];

    const int n_full = n_pts / TILE_PTS;         // 15625 full 256-pt tiles
    const int stride = NBLK * WARPS;             // 2368 warps chip-wide
    const int gw     = bid * WARPS + wid;
    const int count  = (n_full > gw) ? (n_full - gw + stride - 1) / stride : 0;

    const uint32_t ring  = smem_base + (uint32_t)(wid * SLOTS) * TILE_B;
    const uint32_t mring = mbar_base + (uint32_t)(wid * SLOTS) * 8u;

    // ---- prologue: prefetch up to PREF tiles ----
    if (lane == 0) {
        const int pre = count < PREF ? count : PREF;
        for (int j = 0; j < pre; j++) {
            const size_t tile = (size_t)gw + (size_t)j * stride;
            mbar_expect_tx(mring + 8u * j, TILE_B);
            bulk_g2s(ring + (uint32_t)j * TILE_B, pts + tile * (TILE_PTS * 3),
                     TILE_B, mring + 8u * j);
        }
    }

    float obs_sum = 0.0f;

    for (int j = 0; j < count; j++) {
        const int slot = j & (SLOTS - 1);
        mbar_wait_parity(mring + 8u * slot, (uint32_t)((j >> 2) & 1));

        // ---- in-place compute: lane owns bytes [96*lane, 96*lane+96) ----
        char* base = smem_raw + (size_t)(wid * SLOTS + slot) * TILE_B + lane * 96;

        #pragma unroll
        for (int c = 0; c < 4; c++) {
            float2* f2 = (float2*)(base + 24 * c);
            const float2 A = f2[0];
            const float2 B = f2[1];
            const float2 C = f2[2];
            const float p[6] = {A.x, A.y, B.x, B.y, C.x, C.y};
            float o[6];

            #pragma unroll
            for (int i = 0; i < 2; i++) {
                const float d0 = p[3 * i + 0] - Tx;
                const float d1 = p[3 * i + 1] - Ty;
                const float d2 = p[3 * i + 2] - Tz;
                const float v0 = fmaf(d2, R20, fmaf(d1, R10, d0 * R00));
                const float v1 = fmaf(d2, R21, fmaf(d1, R11, d0 * R01));
                const float v2 = fmaf(d2, R22, fmaf(d1, R12, d0 * R02));

                const float ph0 = fmaf(600.0f, v0, 640.0f * v2);
                const float ph1 = fmaf(600.0f, v1, 360.0f * v2);
                // division-free: v2>1 (>0) makes these equivalent to u/w bounds
                const bool m = (v2 > 1.0f) & (v2 < 10.0f) &
                               (ph0 > v2) & (ph0 < 1279.0f * v2) &
                               (ph1 > v2) & (ph1 < 719.0f * v2);

                const float n2 = fmaf(v0, v0, fmaf(v1, v1, v2 * v2));
                const float dist = n2 * rsqrtf(n2);
                const float s = dist - 4.0f;
                // exp(-0.5*((d-4)/2)^2) = exp2(s*s * -(log2 e)/8)
                const float e = exp2f(s * s * -0.18033688f);
                obs_sum += m ? e : 0.0f;

                o[3 * i + 0] = m ? v0 : 0.0f;
                o[3 * i + 1] = m ? v1 : 0.0f;
                o[3 * i + 2] = m ? v2 : 0.0f;
            }
            f2[0] = make_float2(o[0], o[1]);
            f2[1] = make_float2(o[2], o[3]);
            f2[2] = make_float2(o[4], o[5]);
        }

        // make STS visible to the async proxy, then elect-lane issues I/O
        asm volatile("fence.proxy.async.shared::cta;" ::: "memory");
        __syncwarp();

        if (lane == 0) {
            const size_t tile = (size_t)gw + (size_t)j * stride;
            bulk_s2g(out + tile * (TILE_PTS * 3), ring + (uint32_t)slot * TILE_B,
                     TILE_B);
            asm volatile("cp.async.bulk.commit_group;" ::: "memory");

            const int jn = j + PREF;
            if (jn < count) {
                // slot (jn&3) = (j-1)&3 was stored as group j-1; allow only
                // the newest group (j) to still be reading smem before reload
                asm volatile("cp.async.bulk.wait_group.read 1;" ::: "memory");
                const int ns = jn & (SLOTS - 1);
                const size_t tile_n = (size_t)gw + (size_t)jn * stride;
                mbar_expect_tx(mring + 8u * ns, TILE_B);
                bulk_g2s(ring + (uint32_t)ns * TILE_B,
                         pts + tile_n * (TILE_PTS * 3), TILE_B, mring + 8u * ns);
            }
        }
    }

    if (lane == 0) {
        asm volatile("cp.async.bulk.wait_group.read 0;" ::: "memory");
    }

    // ---- tail points (n_pts % 256): scalar on block 0 / thread 0 ----
    if (bid == 0 && t == 0) {
        for (int idx = n_full * TILE_PTS; idx < n_pts; idx++) {
            const float d0 = pts[3 * idx + 0] - Tx;
            const float d1 = pts[3 * idx + 1] - Ty;
            const float d2 = pts[3 * idx + 2] - Tz;
            const float v0 = fmaf(d2, R20, fmaf(d1, R10, d0 * R00));
            const float v1 = fmaf(d2, R21, fmaf(d1, R11, d0 * R01));
            const float v2 = fmaf(d2, R22, fmaf(d1, R12, d0 * R02));
            const float ph0 = fmaf(600.0f, v0, 640.0f * v2);
            const float ph1 = fmaf(600.0f, v1, 360.0f * v2);
            const bool m = (v2 > 1.0f) & (v2 < 10.0f) &
                           (ph0 > v2) & (ph0 < 1279.0f * v2) &
                           (ph1 > v2) & (ph1 < 719.0f * v2);
            const float n2 = fmaf(v0, v0, fmaf(v1, v1, v2 * v2));
            const float dist = n2 * rsqrtf(n2);
            const float s = dist - 4.0f;
            obs_sum += m ? exp2f(s * s * -0.18033688f) : 0.0f;
            out[3 * idx + 0] = m ? v0 : 0.0f;
            out[3 * idx + 1] = m ? v1 : 0.0f;
            out[3 * idx + 2] = m ? v2 : 0.0f;
        }
    }

    // ---- reduction: warp -> block -> global atomic ----
    #pragma unroll
    for (int off = 16; off > 0; off >>= 1)
        obs_sum += __shfl_xor_sync(0xffffffffu, obs_sum, off);

    if (lane == 0) swarp[wid] = obs_sum;
    __syncthreads();

    if (wid == 0) {
        float s = (lane < WARPS) ? swarp[lane] : 0.0f;
        #pragma unroll
        for (int off = 8; off > 0; off >>= 1)
            s += __shfl_xor_sync(0xffffffffu, s, off);
        if (lane == 0) {
            atomicAdd(&g_sum, s);
            __threadfence();
            const unsigned int prev = atomicAdd(&g_count, 1u);
            if (prev == gridDim.x - 1u) {
                const float total = atomicAdd(&g_sum, 0.0f);
                out[loss_idx] = 1.0f / (total + 1e-6f);
                g_sum = 0.0f;       // reset for next graph replay
                g_count = 0u;
            }
        }
    }
}

extern "C" void kernel_launch(void* const* d_in, const int* in_sizes, int n_in,
                              void* d_out, int out_size) {
    const float* pts    = (const float*)d_in[0];
    const float* x      = (const float*)d_in[1];
    const float* y      = (const float*)d_in[2];
    const float* z      = (const float*)d_in[3];
    const float* roll   = (const float*)d_in[4];
    const float* pitch  = (const float*)d_in[5];
    const float* yaw    = (const float*)d_in[6];
    float* out = (float*)d_out;

    const int n_pts = in_sizes[0] / 3;       // 4,000,000
    const int loss_idx = out_size - 1;       // verts first, loss last

    cudaFuncSetAttribute(pose_warp_pipe_kernel,
                         cudaFuncAttributeMaxDynamicSharedMemorySize, SMEM_DYN);
    pose_warp_pipe_kernel<<<NBLK, THREADS, SMEM_DYN>>>(
        pts, x, y, z, roll, pitch, yaw, out, n_pts, loss_idx);
}